// round 4
// baseline (speedup 1.0000x reference)
#include <cuda_runtime.h>
#include <cuda_bf16.h>
#include <math.h>

// ---------------- problem constants ----------------
#define BB    8
#define FREQ  257
#define TT    1345
#define NF    128
#define NS    64
#define NW    20          // (1345-128-1)/64 + 1
#define WIN   (BB*NW)     // 160
#define C1    8
#define P1H   84
#define P1W   41
#define C2    16
#define P2H   28
#define P2W   14
#define HID   6272        // 16*28*14
#define G3    (3*HID)     // 18816

// ---------------- device scratch (no allocation allowed) ----------------
__device__ float g_P1[WIN * C1 * P1H * P1W];   // 160*8*84*41
__device__ float g_FEATS[WIN * HID];           // 160*6272
__device__ float g_GI[(size_t)WIN * G3];       // 160*18816
__device__ float g_H[2][BB * HID];             // ping-pong hidden state

// =====================================================================
// K1: conv1 (1->8ch, 9x9, pad2) + maxpool3 + leaky_relu, fused.
// grid (84, 160), block (41, 8). Each thread: one pooled output (3x3 conv cells).
// =====================================================================
__global__ void conv1_kernel(const float* __restrict__ x,
                             const float* __restrict__ w,
                             const float* __restrict__ bias)
{
    __shared__ float tile[11][132];
    __shared__ float Ws[C1][9][9];

    const int pr  = blockIdx.x;        // pooled row 0..83
    const int win = blockIdx.y;        // 0..159
    const int b   = win / NW;
    const int wdx = win % NW;
    const int tid = threadIdx.y * 41 + threadIdx.x;   // 0..327

    for (int i = tid; i < C1 * 81; i += 328)
        ((float*)Ws)[i] = w[i];

    // window base: x[b][1+r][wdx*64 + c]
    const float* xb = x + (size_t)b * FREQ * TT + TT + wdx * NS;
    const int r0 = 3 * pr - 2;
    for (int i = tid; i < 11 * 132; i += 328) {
        int r = i / 132, c = i % 132;
        int gr = r0 + r, gc = c - 2;
        float v = 0.f;
        if (gr >= 0 && gr < 256 && gc >= 0 && gc < NF)
            v = xb[(size_t)gr * TT + gc];
        tile[r][c] = v;
    }
    __syncthreads();

    const int ch = threadIdx.y;
    const int tc = threadIdx.x;     // pooled col 0..40
    const float bv = bias[ch];
    float acc[3][3];
#pragma unroll
    for (int i = 0; i < 3; i++)
#pragma unroll
        for (int j = 0; j < 3; j++) acc[i][j] = bv;

#pragma unroll
    for (int r = 0; r < 11; r++) {
        float v[11];
#pragma unroll
        for (int m = 0; m < 11; m++) v[m] = tile[r][3 * tc + m];
#pragma unroll
        for (int i = 0; i < 3; i++) {
            const int kr = r - i;
            if (kr >= 0 && kr <= 8) {
#pragma unroll
                for (int kc = 0; kc < 9; kc++) {
                    float wv = Ws[ch][kr][kc];
                    acc[i][0] = fmaf(wv, v[kc],     acc[i][0]);
                    acc[i][1] = fmaf(wv, v[kc + 1], acc[i][1]);
                    acc[i][2] = fmaf(wv, v[kc + 2], acc[i][2]);
                }
            }
        }
    }
    float m = acc[0][0];
#pragma unroll
    for (int i = 0; i < 3; i++)
#pragma unroll
        for (int j = 0; j < 3; j++) m = fmaxf(m, acc[i][j]);
    float o = (m > 0.f) ? m : 0.01f * m;     // lrelu after max (monotone)
    g_P1[(((size_t)win * C1 + ch) * P1H + pr) * P1W + tc] = o;
}

// =====================================================================
// K2: conv2 (8->16ch, 4x4, pad2) + maxpool3 + leaky_relu, fused.
// grid (28, 160), block (14, 16).
// =====================================================================
__global__ void conv2_kernel(const float* __restrict__ w,
                             const float* __restrict__ bias)
{
    __shared__ float tile[C1][6][46];
    __shared__ float Ws[C2][C1][4][4];

    const int pr  = blockIdx.x;     // pooled row 0..27
    const int win = blockIdx.y;
    const int tid = threadIdx.y * 14 + threadIdx.x;   // 0..223

    for (int i = tid; i < C2 * C1 * 16; i += 224)
        ((float*)Ws)[i] = w[i];

    const float* src = g_P1 + (size_t)win * C1 * P1H * P1W;
    const int r0 = 3 * pr - 2;
    for (int i = tid; i < C1 * 6 * 46; i += 224) {
        int ich = i / (6 * 46);
        int rem = i % (6 * 46);
        int r = rem / 46, c = rem % 46;
        int gr = r0 + r, gc = c - 2;
        float v = 0.f;
        if (gr >= 0 && gr < P1H && gc >= 0 && gc < P1W)
            v = src[((size_t)ich * P1H + gr) * P1W + gc];
        tile[ich][r][c] = v;
    }
    __syncthreads();

    const int pc = threadIdx.x;     // pooled col 0..13
    const int oc = threadIdx.y;     // 0..15
    const float bv = bias[oc];
    float acc[3][3];
#pragma unroll
    for (int i = 0; i < 3; i++)
#pragma unroll
        for (int j = 0; j < 3; j++) acc[i][j] = bv;

#pragma unroll
    for (int ich = 0; ich < C1; ich++) {
#pragma unroll
        for (int r = 0; r < 6; r++) {
            float v[6];
#pragma unroll
            for (int m = 0; m < 6; m++) v[m] = tile[ich][r][3 * pc + m];
#pragma unroll
            for (int i = 0; i < 3; i++) {
                const int kr = r - i;
                if (kr >= 0 && kr <= 3) {
#pragma unroll
                    for (int kc = 0; kc < 4; kc++) {
                        float wv = Ws[oc][ich][kr][kc];
                        acc[i][0] = fmaf(wv, v[kc],     acc[i][0]);
                        acc[i][1] = fmaf(wv, v[kc + 1], acc[i][1]);
                        acc[i][2] = fmaf(wv, v[kc + 2], acc[i][2]);
                    }
                }
            }
        }
    }
    float m = acc[0][0];
#pragma unroll
    for (int i = 0; i < 3; i++)
#pragma unroll
        for (int j = 0; j < 3; j++) m = fmaxf(m, acc[i][j]);
    float o = (m > 0.f) ? m : 0.01f * m;
    // feats layout: hid = oc*392 + pr*14 + pc
    g_FEATS[(size_t)win * HID + oc * (P2H * P2W) + pr * P2W + pc] = o;
}

// =====================================================================
// K3: GI = FEATS(160x6272) @ w_ih^T(6272x18816) + b_ih
// Tiled SIMT fp32: BM=160, BN=128, BK=16; 256 threads, 10x8 per thread.
// grid = 147 blocks (one full wave on 148 SMs).
// =====================================================================
__global__ __launch_bounds__(256, 2)
void gi_gemm_kernel(const float* __restrict__ Wih,
                    const float* __restrict__ bih)
{
    __shared__ float As[16][160];
    __shared__ float Bs[16][128];

    const int n0 = blockIdx.x * 128;
    const int tid = threadIdx.x;
    const int ty = tid >> 4;      // 0..15 -> M group (10 rows)
    const int tx = tid & 15;      // 0..15 -> N group (8 cols)

    float acc[10][8];
#pragma unroll
    for (int i = 0; i < 10; i++)
#pragma unroll
        for (int u = 0; u < 8; u++) acc[i][u] = 0.f;

    for (int k0 = 0; k0 < HID; k0 += 16) {
#pragma unroll
        for (int l = 0; l < 10; l++) {
            int idx = tid + l * 256;          // 0..2559
            int m = idx >> 4, kk = idx & 15;
            As[kk][m] = g_FEATS[(size_t)m * HID + k0 + kk];
        }
#pragma unroll
        for (int l = 0; l < 8; l++) {
            int idx = tid + l * 256;          // 0..2047
            int n = idx >> 4, kk = idx & 15;
            Bs[kk][n] = Wih[(size_t)(n0 + n) * HID + k0 + kk];
        }
        __syncthreads();

#pragma unroll
        for (int kk = 0; kk < 16; kk++) {
            float4 b0 = *(const float4*)&Bs[kk][tx * 8];
            float4 b1 = *(const float4*)&Bs[kk][tx * 8 + 4];
            float bb[8] = {b0.x, b0.y, b0.z, b0.w, b1.x, b1.y, b1.z, b1.w};
            float a[10];
#pragma unroll
            for (int i = 0; i < 10; i++) a[i] = As[kk][ty * 10 + i];
#pragma unroll
            for (int i = 0; i < 10; i++)
#pragma unroll
                for (int u = 0; u < 8; u++)
                    acc[i][u] = fmaf(a[i], bb[u], acc[i][u]);
        }
        __syncthreads();
    }

#pragma unroll
    for (int i = 0; i < 10; i++) {
        int m = ty * 10 + i;
#pragma unroll
        for (int u = 0; u < 8; u++) {
            int n = n0 + tx * 8 + u;
            g_GI[(size_t)m * G3 + n] = acc[i][u] + bih[n];
        }
    }
}

// =====================================================================
// K4: one GRU step. grid 392, block 512 (16 warps); warp -> hidden unit j.
// Computes gh for 3 gates x 8 batches, fuses gate nonlinearity, writes h'.
// =====================================================================
__global__ __launch_bounds__(512, 2)
void gru_step_kernel(const float* __restrict__ Whh,
                     const float* __restrict__ bhh,
                     const float* __restrict__ h0,
                     int t)
{
    __shared__ float hs[BB][896];

    const float* hin  = (t == 0) ? h0 : g_H[(t + 1) & 1];
    float*       hout = g_H[t & 1];

    const int warpId = threadIdx.x >> 5;
    const int lane   = threadIdx.x & 31;
    const int j      = blockIdx.x * 16 + warpId;     // 0..6271

    const float* wr = Whh + (size_t)j * HID;
    const float* wz = Whh + (size_t)(j + HID) * HID;
    const float* wn = Whh + (size_t)(j + 2 * HID) * HID;

    float aR[BB], aZ[BB], aN[BB];
#pragma unroll
    for (int b = 0; b < BB; b++) { aR[b] = 0.f; aZ[b] = 0.f; aN[b] = 0.f; }

    for (int ch = 0; ch < 7; ch++) {
        const int kb = ch * 896;
        for (int idx = threadIdx.x; idx < BB * 896; idx += 512) {
            int row = idx / 896, col = idx % 896;
            hs[row][col] = hin[(size_t)row * HID + kb + col];
        }
        __syncthreads();

#pragma unroll 4
        for (int it = 0; it < 28; it++) {
            int k = it * 32 + lane;
            float wrv = wr[kb + k];
            float wzv = wz[kb + k];
            float wnv = wn[kb + k];
#pragma unroll
            for (int b = 0; b < BB; b++) {
                float hv = hs[b][k];
                aR[b] = fmaf(wrv, hv, aR[b]);
                aZ[b] = fmaf(wzv, hv, aZ[b]);
                aN[b] = fmaf(wnv, hv, aN[b]);
            }
        }
        __syncthreads();
    }

    // full warp butterfly reduction: all lanes end with the totals
#pragma unroll
    for (int b = 0; b < BB; b++) {
#pragma unroll
        for (int off = 16; off > 0; off >>= 1) {
            aR[b] += __shfl_xor_sync(0xffffffffu, aR[b], off);
            aZ[b] += __shfl_xor_sync(0xffffffffu, aZ[b], off);
            aN[b] += __shfl_xor_sync(0xffffffffu, aN[b], off);
        }
    }

    if (lane < BB) {
        const int b = lane;
        const float* gib = g_GI + (size_t)(b * NW + t) * G3;
        float ir = gib[j];
        float iz = gib[j + HID];
        float in_ = gib[j + 2 * HID];
        float hr = aR[b] + bhh[j];
        float hz = aZ[b] + bhh[j + HID];
        float hn = aN[b] + bhh[j + 2 * HID];
        float r = 1.f / (1.f + expf(-(ir + hr)));
        float z = 1.f / (1.f + expf(-(iz + hz)));
        float n = tanhf(in_ + r * hn);
        float ho = hin[(size_t)b * HID + j];
        hout[(size_t)b * HID + j] = (1.f - z) * n + z * ho;
    }
}

// =====================================================================
// K5: samples = h @ fc2_w^T + fc2_b ; labels (int32 input) appended as
// float32 values at out[80..87].
// 1 block, 256 threads; warp per dot product.
// =====================================================================
__global__ void final_fc_kernel(const float* __restrict__ fw,
                                const float* __restrict__ fb,
                                const int* __restrict__ labels,
                                float* __restrict__ out)
{
    const float* h = g_H[(NW - 1) & 1];   // g_H[1]
    const int warpId = threadIdx.x >> 5;
    const int lane   = threadIdx.x & 31;

    for (int p = warpId; p < BB * 10; p += 8) {
        int b = p / 10, c = p % 10;
        const float* hb = h + (size_t)b * HID;
        const float* wc = fw + (size_t)c * HID;
        float s = 0.f;
        for (int k = lane; k < HID; k += 32)
            s = fmaf(hb[k], wc[k], s);
#pragma unroll
        for (int off = 16; off > 0; off >>= 1)
            s += __shfl_xor_sync(0xffffffffu, s, off);
        if (lane == 0)
            out[b * 10 + c] = s + fb[c];
    }
    // labels: int32 input values, written as float32 after the 80 samples
    if (threadIdx.x < BB)
        out[BB * 10 + threadIdx.x] = (float)labels[threadIdx.x];
}

// =====================================================================
extern "C" void kernel_launch(void* const* d_in, const int* in_sizes, int n_in,
                              void* d_out, int out_size)
{
    const float* x       = (const float*)d_in[0];
    const int*   labels  = (const int*)d_in[1];
    const float* h0      = (const float*)d_in[2];
    const float* conv1_w = (const float*)d_in[3];
    const float* conv1_b = (const float*)d_in[4];
    const float* conv2_w = (const float*)d_in[5];
    const float* conv2_b = (const float*)d_in[6];
    const float* w_ih    = (const float*)d_in[7];
    const float* w_hh    = (const float*)d_in[8];
    const float* b_ih    = (const float*)d_in[9];
    const float* b_hh    = (const float*)d_in[10];
    const float* fc2_w   = (const float*)d_in[11];
    const float* fc2_b   = (const float*)d_in[12];
    float*       out     = (float*)d_out;

    conv1_kernel<<<dim3(P1H, WIN), dim3(41, 8)>>>(x, conv1_w, conv1_b);
    conv2_kernel<<<dim3(P2H, WIN), dim3(14, 16)>>>(conv2_w, conv2_b);
    gi_gemm_kernel<<<G3 / 128, 256>>>(w_ih, b_ih);
    for (int t = 0; t < NW; t++)
        gru_step_kernel<<<HID / 16, 512>>>(w_hh, b_hh, h0, t);
    final_fc_kernel<<<1, 256>>>(fc2_w, fc2_b, labels, out);
}